// round 12
// baseline (speedup 1.0000x reference)
#include <cuda_runtime.h>
#include <cuda_fp16.h>
#include <stdint.h>
#include <math.h>

#define BSZ 16384
#define DM  512
#define NS  (BSZ*DM)
#define EPSLN 1e-6f

// ---------------- device-global scratch ----------------
__device__ __half g_inh[3*NS];                 // input hi
__device__ __half g_ph [3*NS], g_pl [3*NS];    // proj hi/lo (lo for exact residual)
__device__ __half g_chh[3*NS];                 // ctx hi (rows = B*3)
__device__ __half g_w2h[NS];                   // weighted hi
__device__ __half g_q16[3*NS], g_k16[3*NS], g_v16[3*NS];  // [B,3,512] fp16
// transposed fp16 weights ([N,K] row-major); WQ/WK/WV contiguous
#define OFF_WF  0
#define OFF_WR  262144
#define OFF_WM  524288
#define OFF_WQ  786432
#define OFF_WK  1048576
#define OFF_WV  1310720
#define OFF_WO  1572864
#define OFF_WG  1835008
#define OFF_WA1 2097152
#define WT_TOTAL (2097152 + 393216)
__device__ __half g_bwh[WT_TOTAL];
__device__ float g_bqkv[1536];
// fp32 scratch
__device__ float g_h [BSZ*256];
__device__ float g_aw[BSZ*3];
__device__ float g_o [3*NS];
__device__ float g_wt[NS], g_gl[NS];

// ---------------- PTX helpers ----------------
__device__ __forceinline__ uint32_t smem_u32(const void* p) {
    uint32_t a;
    asm("{ .reg .u64 t; cvta.to.shared.u64 t, %1; cvt.u32.u64 %0, t; }" : "=r"(a) : "l"(p));
    return a;
}
#define CP16(sm, gp) \
    asm volatile("cp.async.cg.shared.global [%0], [%1], 16;" :: "r"(sm), "l"(gp) : "memory")
#define CP_COMMIT() asm volatile("cp.async.commit_group;" ::: "memory")
#define CP_WAIT4()  asm volatile("cp.async.wait_group 4;" ::: "memory")
#define LDSM4(d, a) \
    asm volatile("ldmatrix.sync.aligned.m8n8.x4.shared.b16 {%0,%1,%2,%3}, [%4];" \
        : "=r"((d)[0]), "=r"((d)[1]), "=r"((d)[2]), "=r"((d)[3]) : "r"(a))
#define LDSM2(d, a) \
    asm volatile("ldmatrix.sync.aligned.m8n8.x2.shared.b16 {%0,%1}, [%2];" \
        : "=r"((d)[0]), "=r"((d)[1]) : "r"(a))
__device__ __forceinline__ void mma16816(float* c, const uint32_t* a, const uint32_t* b) {
    asm volatile("mma.sync.aligned.m16n8k16.row.col.f32.f16.f16.f32 "
        "{%0,%1,%2,%3}, {%4,%5,%6,%7}, {%8,%9}, {%0,%1,%2,%3};"
        : "+f"(c[0]), "+f"(c[1]), "+f"(c[2]), "+f"(c[3])
        : "r"(a[0]), "r"(a[1]), "r"(a[2]), "r"(a[3]), "r"(b[0]), "r"(b[1]));
}

// ---------------- pure fp16 GEMM: tile 128x64x32, 256 thr, warp 32x32 ----------
// XOR-swizzled 64B rows. 6-stage cp.async (5-chunk prefetch), 1 barrier/chunk.
// smem/stage: A 8K + B 4K = 12K; x6 = 72K; 3 CTAs/SM (register-fit).
#define S_AH   0
#define S_BH   8192
#define STAGEB 12288
#define NSTG   6
__device__ __forceinline__ uint32_t swz(int row, int u) {
    return (uint32_t)(row * 64 + ((u ^ ((row >> 1) & 3)) << 4));
}
// OUT: 0 = fp32, 1 = fp16 hi/lo, 2 = fp16 hi only

template <int RELU, int OUT>
__device__ __forceinline__ void gemm_mma(
    const __half* __restrict__ a_h0, const __half* __restrict__ a_h1,
    const __half* __restrict__ a_h2,
    int lda, int nchunks,
    const __half* __restrict__ b_h, int ldb,
    const float* __restrict__ bias,
    float* __restrict__ cf, int ldc,
    __half* __restrict__ c_hi, __half* __restrict__ c_lo, int ldcb)
{
    extern __shared__ char dsm[];
    const uint32_t smem = smem_u32(dsm);
    const int tid  = threadIdx.x;
    const int lane = tid & 31;
    const int warp = tid >> 5;
    const int wm = warp & 3;    // 0..3 (32 rows)
    const int wn = warp >> 2;   // 0..1 (32 cols)
    const int m0 = blockIdx.y * 128;
    const int n0 = blockIdx.x * 64;

    float acc[2][4][4];
#pragma unroll
    for (int i = 0; i < 2; i++)
#pragma unroll
        for (int j = 0; j < 4; j++)
#pragma unroll
            for (int k = 0; k < 4; k++) acc[i][j][k] = 0.f;

    const int arow = tid >> 1;
    const int au   = (tid & 1) * 2;
    const int brow = tid >> 2;
    const int bu   = tid & 3;
    const uint32_t aswz0 = swz(arow, au);
    const uint32_t aswz1 = swz(arow, au + 1);
    const uint32_t bswz  = swz(brow, bu);

    auto load_stage = [&](int st, int kc) {
        int seg = kc >> 4;
        const __half* ah = (seg == 0) ? a_h0 : (seg == 1) ? a_h1 : a_h2;
        size_t abase = (size_t)(m0 + arow) * lda + (kc & 15) * 32;
        uint32_t sb = smem + st * STAGEB;
        CP16(sb + S_AH + aswz0, ah + abase + au * 8);
        CP16(sb + S_AH + aswz1, ah + abase + au * 8 + 8);
        CP16(sb + S_BH + bswz, b_h + (size_t)(n0 + brow) * ldb + kc * 32 + bu * 8);
    };

    int ar0 = wm * 32 + (lane & 15);
    int ar1 = ar0 + 16;
    const uint32_t aBase0 = (uint32_t)(ar0 * 64), aSw0 = (uint32_t)((ar0 >> 1) & 3);
    const uint32_t aBase1 = (uint32_t)(ar1 * 64), aSw1 = (uint32_t)((ar1 >> 1) & 3);
    const uint32_t ua0 = (uint32_t)(lane >> 4);
    int br_ = wn * 32 + (lane & 7);
    const uint32_t ub0 = (uint32_t)((lane >> 3) & 1);
    uint32_t bBase[4], bSw[4];
#pragma unroll
    for (int nt = 0; nt < 4; nt++) {
        int r = br_ + nt * 8;
        bBase[nt] = (uint32_t)(r * 64);
        bSw[nt]   = (uint32_t)((r >> 1) & 3);
    }

    auto compute_stage = [&](int st) {
        uint32_t base = smem + st * STAGEB;
#pragma unroll
        for (int k16 = 0; k16 < 2; k16++) {
            uint32_t ua = ua0 + 2 * k16;
            uint32_t ub = ub0 + 2 * k16;
            uint32_t a[2][4], b[4][2];
#pragma unroll
            for (int nt = 0; nt < 4; nt++)
                LDSM2(b[nt], base + S_BH + bBase[nt] + ((ub ^ bSw[nt]) << 4));
            LDSM4(a[0], base + S_AH + aBase0 + ((ua ^ aSw0) << 4));
            LDSM4(a[1], base + S_AH + aBase1 + ((ua ^ aSw1) << 4));
#pragma unroll
            for (int mt = 0; mt < 2; mt++)
#pragma unroll
                for (int nt = 0; nt < 4; nt++) mma16816(acc[mt][nt], a[mt], b[nt]);
        }
    };

    // 5-chunk prologue (bounded by nchunks)
    int npro = (nchunks < 5) ? nchunks : 5;
    for (int c = 0; c < npro; c++) { load_stage(c, c); CP_COMMIT(); }
    for (int c = npro; c < 5; c++) CP_COMMIT();   // keep group count consistent
    for (int kc = 0; kc < nchunks; kc++) {
        CP_WAIT4();
        __syncthreads();
        if (kc + 5 < nchunks) load_stage((kc + 5) % NSTG, kc + 5);
        CP_COMMIT();
        compute_stage(kc % NSTG);
    }

    // epilogue
#pragma unroll
    for (int mt = 0; mt < 2; mt++) {
        int r0 = m0 + wm * 32 + mt * 16 + (lane >> 2);
        int r1 = r0 + 8;
#pragma unroll
        for (int nt = 0; nt < 4; nt++) {
            int cc = n0 + wn * 32 + nt * 8 + (lane & 3) * 2;
            float b0 = bias[cc], b1 = bias[cc + 1];
            float v00 = acc[mt][nt][0] + b0, v01 = acc[mt][nt][1] + b1;
            float v10 = acc[mt][nt][2] + b0, v11 = acc[mt][nt][3] + b1;
            if (RELU) {
                v00 = fmaxf(v00, 0.f); v01 = fmaxf(v01, 0.f);
                v10 = fmaxf(v10, 0.f); v11 = fmaxf(v11, 0.f);
            }
            if (OUT == 0) {
                *(float2*)(cf + (size_t)r0 * ldc + cc) = make_float2(v00, v01);
                *(float2*)(cf + (size_t)r1 * ldc + cc) = make_float2(v10, v11);
            } else if (OUT == 1) {
                __half h00 = __float2half_rn(v00), h01 = __float2half_rn(v01);
                __half h10 = __float2half_rn(v10), h11 = __float2half_rn(v11);
                __half2 p0, p1, l0, l1;
                p0.x = h00; p0.y = h01; p1.x = h10; p1.y = h11;
                l0.x = __float2half_rn(v00 - __half2float(h00));
                l0.y = __float2half_rn(v01 - __half2float(h01));
                l1.x = __float2half_rn(v10 - __half2float(h10));
                l1.y = __float2half_rn(v11 - __half2float(h11));
                *(__half2*)(c_hi + (size_t)r0 * ldcb + cc) = p0;
                *(__half2*)(c_hi + (size_t)r1 * ldcb + cc) = p1;
                *(__half2*)(c_lo + (size_t)r0 * ldcb + cc) = l0;
                *(__half2*)(c_lo + (size_t)r1 * ldcb + cc) = l1;
            } else {
                *(__half2*)(c_hi + (size_t)r0 * ldcb + cc) = __floats2half2_rn(v00, v01);
                *(__half2*)(c_hi + (size_t)r1 * ldcb + cc) = __floats2half2_rn(v10, v11);
            }
        }
    }
}

// ---------------- GEMM wrappers ----------------
__global__ __launch_bounds__(256, 3)
void k_gemm_proj(const float* __restrict__ bf, const float* __restrict__ br,
                 const float* __restrict__ bm)
{
    int z = blockIdx.z;
    const __half* ah = g_inh + (size_t)z * NS;
    int off = (z == 0) ? OFF_WF : (z == 1) ? OFF_WR : OFF_WM;
    const float* bias = (z == 0) ? bf : (z == 1) ? br : bm;
    gemm_mma<0, 1>(ah, ah, ah, 512, 16, g_bwh + off, 512, bias,
                   nullptr, 0, g_ph + (size_t)z * NS, g_pl + (size_t)z * NS, 512);
}

__global__ __launch_bounds__(256, 3)
void k_gemm_qkv()
{
    int s = blockIdx.z;
    const __half* ah = g_ph + (size_t)s * NS;
    int n0 = blockIdx.x * 64;
    int w = n0 >> 9;  // 0=q, 1=k, 2=v
    __half* buf = (w == 0) ? g_q16 : (w == 1) ? g_k16 : g_v16;
    __half* oh = buf + (size_t)s * 512 - (size_t)w * 512;
    gemm_mma<0, 2>(ah, ah, ah, 512, 16, g_bwh + OFF_WQ, 512, g_bqkv,
                   nullptr, 0, oh, nullptr, 1536);
}

__global__ __launch_bounds__(256, 3)
void k_gemm_h(const float* __restrict__ ba1)
{
    gemm_mma<1, 0>(g_ph, g_ph + NS, g_ph + 2 * (size_t)NS,
                   512, 48, g_bwh + OFF_WA1, 1536, ba1,
                   g_h, 256, nullptr, nullptr, 0);
}

__global__ __launch_bounds__(256, 3)
void k_gemm_o(const float* __restrict__ bo)
{
    gemm_mma<0, 0>(g_chh, g_chh, g_chh, 512, 16,
                   g_bwh + OFF_WO, 512, bo, g_o, 512, nullptr, nullptr, 0);
}

__global__ __launch_bounds__(256, 3)
void k_gemm_gate(const float* __restrict__ bg)
{
    gemm_mma<0, 0>(g_w2h, g_w2h, g_w2h, 512, 16,
                   g_bwh + OFF_WG, 512, bg, g_gl, 512, nullptr, nullptr, 0);
}

// ---------------- prep kernels ----------------
__global__ __launch_bounds__(256)
void k_split3(const float* __restrict__ x0, const float* __restrict__ x1,
              const float* __restrict__ x2)
{
    int z = blockIdx.z;
    const float* x = (z == 0) ? x0 : (z == 1) ? x1 : x2;
    __half* h = g_inh + (size_t)z * NS;
    int i = blockIdx.x * 256 + threadIdx.x;
    float4 v = ((const float4*)x)[i];
    ((__half2*)h)[2 * i]     = __floats2half2_rn(v.x, v.y);
    ((__half2*)h)[2 * i + 1] = __floats2half2_rn(v.z, v.w);
}

__global__ __launch_bounds__(256)
void k_tw_all(const float* __restrict__ W0, const float* __restrict__ W1,
              const float* __restrict__ W2, const float* __restrict__ W3,
              const float* __restrict__ W4, const float* __restrict__ W5,
              const float* __restrict__ W6, const float* __restrict__ W7,
              const float* __restrict__ W8)
{
    int z = blockIdx.z;
    const float* W;
    int R, C, off;
    switch (z) {
        case 0: W = W0; R = 512;  C = 512; off = OFF_WF;  break;
        case 1: W = W1; R = 512;  C = 512; off = OFF_WR;  break;
        case 2: W = W2; R = 512;  C = 512; off = OFF_WM;  break;
        case 3: W = W3; R = 512;  C = 512; off = OFF_WQ;  break;
        case 4: W = W4; R = 512;  C = 512; off = OFF_WK;  break;
        case 5: W = W5; R = 512;  C = 512; off = OFF_WV;  break;
        case 6: W = W6; R = 512;  C = 512; off = OFF_WO;  break;
        case 7: W = W7; R = 512;  C = 512; off = OFF_WG;  break;
        default: W = W8; R = 1536; C = 256; off = OFF_WA1; break;
    }
    int bx = blockIdx.x * 32, by = blockIdx.y * 32;
    if (bx >= C || by >= R) return;
    __shared__ float t[32][33];
    int x = threadIdx.x & 31, y = (threadIdx.x >> 5) * 4;
#pragma unroll
    for (int j = 0; j < 4; j++) t[y + j][x] = W[(size_t)(by + y + j) * C + bx + x];
    __syncthreads();
    __half* oh = g_bwh + off;
#pragma unroll
    for (int j = 0; j < 4; j++) {
        int n = bx + y + j, k = by + x;
        oh[(size_t)n * R + k] = __float2half_rn(t[x][y + j]);
    }
}

__global__ void k_bias(const float* __restrict__ bq, const float* __restrict__ bk,
                       const float* __restrict__ bv)
{
    int z = blockIdx.x, i = threadIdx.x;
    const float* b = (z == 0) ? bq : (z == 1) ? bk : bv;
    g_bqkv[z * 512 + i] = b[i];
}

// ---------------- small fused kernels ----------------
__global__ __launch_bounds__(128)
void k_aw(const float* __restrict__ Wa2, const float* __restrict__ ba2)
{
    int row = blockIdx.x * 4 + (threadIdx.x >> 5);
    int l = threadIdx.x & 31;
    const float* hr = g_h + (size_t)row * 256;
    float a0 = 0.f, a1 = 0.f, a2 = 0.f;
#pragma unroll
    for (int i = l; i < 256; i += 32) {
        float hv = hr[i];
        a0 = fmaf(hv, Wa2[i * 3 + 0], a0);
        a1 = fmaf(hv, Wa2[i * 3 + 1], a1);
        a2 = fmaf(hv, Wa2[i * 3 + 2], a2);
    }
#pragma unroll
    for (int off = 16; off; off >>= 1) {
        a0 += __shfl_xor_sync(0xffffffffu, a0, off);
        a1 += __shfl_xor_sync(0xffffffffu, a1, off);
        a2 += __shfl_xor_sync(0xffffffffu, a2, off);
    }
    if (l == 0) {
        a0 += ba2[0]; a1 += ba2[1]; a2 += ba2[2];
        float mx = fmaxf(a0, fmaxf(a1, a2));
        float e0 = expf(a0 - mx), e1 = expf(a1 - mx), e2 = expf(a2 - mx);
        float inv = 1.f / (e0 + e1 + e2);
        g_aw[row * 3 + 0] = e0 * inv;
        g_aw[row * 3 + 1] = e1 * inv;
        g_aw[row * 3 + 2] = e2 * inv;
    }
}

__device__ __forceinline__ float4 ldh4(const __half* p)
{
    uint2 u = *(const uint2*)p;
    __half2 a = *(__half2*)&u.x, b = *(__half2*)&u.y;
    float2 fa = __half22float2(a), fb = __half22float2(b);
    return make_float4(fa.x, fa.y, fb.x, fb.y);
}
__device__ __forceinline__ float d4(float4 a, float4 b)
{ return a.x * b.x + a.y * b.y + a.z * b.z + a.w * b.w; }

__global__ __launch_bounds__(128)
void k_attn()
{
    int b = blockIdx.x;
    int h = threadIdx.x >> 5;
    int l = threadIdx.x & 31;
    size_t base = (size_t)b * 1536 + h * 128 + l * 4;
    float4 q0 = ldh4(&g_q16[base]);
    float4 q1 = ldh4(&g_q16[base + 512]);
    float4 q2 = ldh4(&g_q16[base + 1024]);
    float4 k0 = ldh4(&g_k16[base]);
    float4 k1 = ldh4(&g_k16[base + 512]);
    float4 k2 = ldh4(&g_k16[base + 1024]);
    float4 v0 = ldh4(&g_v16[base]);
    float4 v1 = ldh4(&g_v16[base + 512]);
    float4 v2 = ldh4(&g_v16[base + 1024]);

    float sc[3][3];
    sc[0][0] = d4(q0, k0); sc[0][1] = d4(q0, k1); sc[0][2] = d4(q0, k2);
    sc[1][0] = d4(q1, k0); sc[1][1] = d4(q1, k1); sc[1][2] = d4(q1, k2);
    sc[2][0] = d4(q2, k0); sc[2][1] = d4(q2, k1); sc[2][2] = d4(q2, k2);
#pragma unroll
    for (int qi = 0; qi < 3; qi++)
#pragma unroll
        for (int si = 0; si < 3; si++)
#pragma unroll
            for (int off = 16; off; off >>= 1)
                sc[qi][si] += __shfl_xor_sync(0xffffffffu, sc[qi][si], off);

    const float scale = 0.088388347648318447f;
#pragma unroll
    for (int qi = 0; qi < 3; qi++) {
        float s0 = sc[qi][0] * scale, s1 = sc[qi][1] * scale, s2 = sc[qi][2] * scale;
        float mx = fmaxf(s0, fmaxf(s1, s2));
        float e0 = expf(s0 - mx), e1 = expf(s1 - mx), e2 = expf(s2 - mx);
        float inv = 1.f / (e0 + e1 + e2);
        float a0 = e0 * inv, a1 = e1 * inv, a2 = e2 * inv;
        float4 c;
        c.x = a0 * v0.x + a1 * v1.x + a2 * v2.x;
        c.y = a0 * v0.y + a1 * v1.y + a2 * v2.y;
        c.z = a0 * v0.z + a1 * v1.z + a2 * v2.z;
        c.w = a0 * v0.w + a1 * v1.w + a2 * v2.w;
        size_t ob = base + (size_t)qi * 512;
        ((__half2*)&g_chh[ob])[0] = __floats2half2_rn(c.x, c.y);
        ((__half2*)&g_chh[ob])[1] = __floats2half2_rn(c.z, c.w);
    }
}

__device__ __forceinline__ void block_reduce2(float& s, float& q, float* ss, float* sq)
{
#pragma unroll
    for (int off = 16; off; off >>= 1) {
        s += __shfl_xor_sync(0xffffffffu, s, off);
        q += __shfl_xor_sync(0xffffffffu, q, off);
    }
    int w = threadIdx.x >> 5;
    if ((threadIdx.x & 31) == 0) { ss[w] = s; sq[w] = q; }
    __syncthreads();
    s = ss[0] + ss[1] + ss[2] + ss[3];
    q = sq[0] + sq[1] + sq[2] + sq[3];
    __syncthreads();
}

__device__ __forceinline__ float4 rec4(const __half* hp, const __half* lp)
{
    float4 h = ldh4(hp), l = ldh4(lp);
    return make_float4(h.x + l.x, h.y + l.y, h.z + l.z, h.w + l.w);
}

__global__ __launch_bounds__(128)
void k_post1(const float* __restrict__ gamma1, const float* __restrict__ beta1)
{
    __shared__ float ss[4], sq[4];
    int b = blockIdx.x;
    int d = threadIdx.x * 4;
    float aw0 = g_aw[b * 3 + 0], aw1 = g_aw[b * 3 + 1], aw2 = g_aw[b * 3 + 2];
    float4 gm = *(const float4*)&gamma1[d];
    float4 be = *(const float4*)&beta1[d];
    float4 wacc = make_float4(0.f, 0.f, 0.f, 0.f);
#pragma unroll
    for (int s = 0; s < 3; s++) {
        size_t px = (size_t)s * NS + (size_t)b * 512 + d;
        float4 xv = rec4(&g_ph[px], &g_pl[px]);
        float4 ov = *(const float4*)&g_o[((size_t)b * 3 + s) * 512 + d];
        float4 v;
        v.x = xv.x + ov.x; v.y = xv.y + ov.y; v.z = xv.z + ov.z; v.w = xv.w + ov.w;
        float lsum = v.x + v.y + v.z + v.w;
        float lsq  = v.x * v.x + v.y * v.y + v.z * v.z + v.w * v.w;
        block_reduce2(lsum, lsq, ss, sq);
        float mean = lsum * (1.f / 512.f);
        float var  = lsq * (1.f / 512.f) - mean * mean;
        float inv  = rsqrtf(var + EPSLN);
        float a = (s == 0) ? aw0 : (s == 1) ? aw1 : aw2;
        wacc.x += a * (gm.x * (v.x - mean) * inv + be.x);
        wacc.y += a * (gm.y * (v.y - mean) * inv + be.y);
        wacc.z += a * (gm.z * (v.z - mean) * inv + be.z);
        wacc.w += a * (gm.w * (v.w - mean) * inv + be.w);
    }
    size_t ob = (size_t)b * 512 + d;
    *(float4*)&g_wt[ob] = wacc;
    ((__half2*)&g_w2h[ob])[0] = __floats2half2_rn(wacc.x, wacc.y);
    ((__half2*)&g_w2h[ob])[1] = __floats2half2_rn(wacc.z, wacc.w);
}

__device__ __forceinline__ float sigm(float x) { return 1.f / (1.f + expf(-x)); }

__global__ __launch_bounds__(128)
void k_post2(const float* __restrict__ gamma2, const float* __restrict__ beta2,
             float* __restrict__ out)
{
    __shared__ float ss[4], sq[4];
    int b = blockIdx.x;
    int d = threadIdx.x * 4;
    size_t ob = (size_t)b * 512 + d;
    float4 wv = *(const float4*)&g_wt[ob];
    float4 gl = *(const float4*)&g_gl[ob];
    size_t pm = 2 * (size_t)NS + ob;
    float4 mp = rec4(&g_ph[pm], &g_pl[pm]);
    float4 t;
    t.x = mp.x + sigm(gl.x) * wv.x;
    t.y = mp.y + sigm(gl.y) * wv.y;
    t.z = mp.z + sigm(gl.z) * wv.z;
    t.w = mp.w + sigm(gl.w) * wv.w;
    float lsum = t.x + t.y + t.z + t.w;
    float lsq  = t.x * t.x + t.y * t.y + t.z * t.z + t.w * t.w;
    block_reduce2(lsum, lsq, ss, sq);
    float mean = lsum * (1.f / 512.f);
    float var  = lsq * (1.f / 512.f) - mean * mean;
    float inv  = rsqrtf(var + EPSLN);
    float4 gm = *(const float4*)&gamma2[d];
    float4 be = *(const float4*)&beta2[d];
    float4 r;
    r.x = gm.x * (t.x - mean) * inv + be.x;
    r.y = gm.y * (t.y - mean) * inv + be.y;
    r.z = gm.z * (t.z - mean) * inv + be.z;
    r.w = gm.w * (t.w - mean) * inv + be.w;
    *(float4*)&out[ob] = r;
}

// ---------------- launch ----------------
extern "C" void kernel_launch(void* const* d_in, const int* in_sizes, int n_in,
                              void* d_out, int out_size)
{
    const float* frontier = (const float*)d_in[0];
    const float* cross    = (const float*)d_in[1];
    const float* mapf     = (const float*)d_in[2];
    const float* Wf  = (const float*)d_in[3];
    const float* bf  = (const float*)d_in[4];
    const float* Wr  = (const float*)d_in[5];
    const float* br  = (const float*)d_in[6];
    const float* Wm  = (const float*)d_in[7];
    const float* bm  = (const float*)d_in[8];
    const float* Wa1 = (const float*)d_in[9];
    const float* ba1 = (const float*)d_in[10];
    const float* Wa2 = (const float*)d_in[11];
    const float* ba2 = (const float*)d_in[12];
    const float* Wq  = (const float*)d_in[13];
    const float* bq  = (const float*)d_in[14];
    const float* Wk  = (const float*)d_in[15];
    const float* bk  = (const float*)d_in[16];
    const float* Wv  = (const float*)d_in[17];
    const float* bv  = (const float*)d_in[18];
    const float* Wo  = (const float*)d_in[19];
    const float* bo  = (const float*)d_in[20];
    const float* Wg  = (const float*)d_in[21];
    const float* bg  = (const float*)d_in[22];
    const float* gamma1 = (const float*)d_in[23];
    const float* beta1  = (const float*)d_in[24];
    const float* gamma2 = (const float*)d_in[25];
    const float* beta2  = (const float*)d_in[26];

    cudaFuncSetAttribute(k_gemm_proj, cudaFuncAttributeMaxDynamicSharedMemorySize, NSTG * STAGEB);
    cudaFuncSetAttribute(k_gemm_qkv,  cudaFuncAttributeMaxDynamicSharedMemorySize, NSTG * STAGEB);
    cudaFuncSetAttribute(k_gemm_h,    cudaFuncAttributeMaxDynamicSharedMemorySize, NSTG * STAGEB);
    cudaFuncSetAttribute(k_gemm_o,    cudaFuncAttributeMaxDynamicSharedMemorySize, NSTG * STAGEB);
    cudaFuncSetAttribute(k_gemm_gate, cudaFuncAttributeMaxDynamicSharedMemorySize, NSTG * STAGEB);

    k_split3<<<dim3(8192, 1, 3), 256>>>(frontier, cross, mapf);
    k_tw_all<<<dim3(16, 48, 9), 256>>>(Wf, Wr, Wm, Wq, Wk, Wv, Wo, Wg, Wa1);
    k_bias<<<3, 512>>>(bq, bk, bv);

    k_gemm_proj<<<dim3(8, 128, 3), 256, NSTG * STAGEB>>>(bf, br, bm);
    k_gemm_h<<<dim3(4, 128, 1), 256, NSTG * STAGEB>>>(ba1);
    k_aw<<<BSZ / 4, 128>>>(Wa2, ba2);
    k_gemm_qkv<<<dim3(24, 128, 3), 256, NSTG * STAGEB>>>();
    k_attn<<<BSZ, 128>>>();
    k_gemm_o<<<dim3(8, 384, 1), 256, NSTG * STAGEB>>>(bo);
    k_post1<<<BSZ, 128>>>(gamma1, beta1);
    k_gemm_gate<<<dim3(8, 128, 1), 256, NSTG * STAGEB>>>(bg);
    k_post2<<<BSZ, 128>>>(gamma2, beta2, (float*)d_out);
}

// round 13
// speedup vs baseline: 1.0432x; 1.0432x over previous
#include <cuda_runtime.h>
#include <cuda_fp16.h>
#include <stdint.h>
#include <math.h>

#define BSZ 16384
#define DM  512
#define NS  (BSZ*DM)
#define EPSLN 1e-6f

// ---------------- device-global scratch ----------------
__device__ __half g_inh[3*NS];                 // input hi
__device__ __half g_ph [3*NS], g_pl [3*NS];    // proj hi/lo (lo for exact residual)
__device__ __half g_chh[3*NS];                 // ctx hi (rows = B*3)
__device__ __half g_w2h[NS];                   // weighted hi
__device__ __half g_q16[3*NS], g_k16[3*NS], g_v16[3*NS];  // [B,3,512] fp16
// transposed fp16 weights ([N,K] row-major); WQ/WK/WV contiguous
#define OFF_WF  0
#define OFF_WR  262144
#define OFF_WM  524288
#define OFF_WQ  786432
#define OFF_WK  1048576
#define OFF_WV  1310720
#define OFF_WO  1572864
#define OFF_WG  1835008
#define OFF_WA1 2097152
#define WT_TOTAL (2097152 + 393216)
__device__ __half g_bwh[WT_TOTAL];
__device__ float g_bqkv[1536];
// fp32 scratch
__device__ float g_h [BSZ*256];
__device__ float g_aw[BSZ*3];
__device__ float g_o [3*NS];
__device__ float g_wt[NS], g_gl[NS];

// ---------------- PTX helpers ----------------
__device__ __forceinline__ uint32_t smem_u32(const void* p) {
    uint32_t a;
    asm("{ .reg .u64 t; cvta.to.shared.u64 t, %1; cvt.u32.u64 %0, t; }" : "=r"(a) : "l"(p));
    return a;
}
#define CP16(sm, gp) \
    asm volatile("cp.async.cg.shared.global [%0], [%1], 16;" :: "r"(sm), "l"(gp) : "memory")
#define CP_COMMIT() asm volatile("cp.async.commit_group;" ::: "memory")
#define CP_WAIT2()  asm volatile("cp.async.wait_group 2;" ::: "memory")
#define LDSM4(d, a) \
    asm volatile("ldmatrix.sync.aligned.m8n8.x4.shared.b16 {%0,%1,%2,%3}, [%4];" \
        : "=r"((d)[0]), "=r"((d)[1]), "=r"((d)[2]), "=r"((d)[3]) : "r"(a))
#define LDSM2(d, a) \
    asm volatile("ldmatrix.sync.aligned.m8n8.x2.shared.b16 {%0,%1}, [%2];" \
        : "=r"((d)[0]), "=r"((d)[1]) : "r"(a))
__device__ __forceinline__ void mma16816(float* c, const uint32_t* a, const uint32_t* b) {
    asm volatile("mma.sync.aligned.m16n8k16.row.col.f32.f16.f16.f32 "
        "{%0,%1,%2,%3}, {%4,%5,%6,%7}, {%8,%9}, {%0,%1,%2,%3};"
        : "+f"(c[0]), "+f"(c[1]), "+f"(c[2]), "+f"(c[3])
        : "r"(a[0]), "r"(a[1]), "r"(a[2]), "r"(a[3]), "r"(b[0]), "r"(b[1]));
}

// ---------------- pure fp16 GEMM: tile 128x64x32, 256 thr, warp 32x32 ----------
// (R9 core: proven local optimum)
#define S_AH   0
#define S_BH   8192
#define STAGEB 12288
#define NSTG   4
__device__ __forceinline__ uint32_t swz(int row, int u) {
    return (uint32_t)(row * 64 + ((u ^ ((row >> 1) & 3)) << 4));
}
// OUT: 0 = fp32, 1 = fp16 hi/lo, 2 = fp16 hi only

template <int RELU, int OUT>
__device__ __forceinline__ void gemm_mma(
    const __half* __restrict__ a_h0, const __half* __restrict__ a_h1,
    const __half* __restrict__ a_h2,
    int lda, int nchunks,
    const __half* __restrict__ b_h, int ldb,
    const float* __restrict__ bias,
    float* __restrict__ cf, int ldc,
    __half* __restrict__ c_hi, __half* __restrict__ c_lo, int ldcb)
{
    extern __shared__ char dsm[];
    const uint32_t smem = smem_u32(dsm);
    const int tid  = threadIdx.x;
    const int lane = tid & 31;
    const int warp = tid >> 5;
    const int wm = warp & 3;
    const int wn = warp >> 2;
    const int m0 = blockIdx.y * 128;
    const int n0 = blockIdx.x * 64;

    float acc[2][4][4];
#pragma unroll
    for (int i = 0; i < 2; i++)
#pragma unroll
        for (int j = 0; j < 4; j++)
#pragma unroll
            for (int k = 0; k < 4; k++) acc[i][j][k] = 0.f;

    const int arow = tid >> 1;
    const int au   = (tid & 1) * 2;
    const int brow = tid >> 2;
    const int bu   = tid & 3;
    const uint32_t aswz0 = swz(arow, au);
    const uint32_t aswz1 = swz(arow, au + 1);
    const uint32_t bswz  = swz(brow, bu);

    auto load_stage = [&](int st, int kc) {
        int seg = kc >> 4;
        const __half* ah = (seg == 0) ? a_h0 : (seg == 1) ? a_h1 : a_h2;
        size_t abase = (size_t)(m0 + arow) * lda + (kc & 15) * 32;
        uint32_t sb = smem + st * STAGEB;
        CP16(sb + S_AH + aswz0, ah + abase + au * 8);
        CP16(sb + S_AH + aswz1, ah + abase + au * 8 + 8);
        CP16(sb + S_BH + bswz, b_h + (size_t)(n0 + brow) * ldb + kc * 32 + bu * 8);
    };

    int ar0 = wm * 32 + (lane & 15);
    int ar1 = ar0 + 16;
    const uint32_t aBase0 = (uint32_t)(ar0 * 64), aSw0 = (uint32_t)((ar0 >> 1) & 3);
    const uint32_t aBase1 = (uint32_t)(ar1 * 64), aSw1 = (uint32_t)((ar1 >> 1) & 3);
    const uint32_t ua0 = (uint32_t)(lane >> 4);
    int br_ = wn * 32 + (lane & 7);
    const uint32_t ub0 = (uint32_t)((lane >> 3) & 1);
    uint32_t bBase[4], bSw[4];
#pragma unroll
    for (int nt = 0; nt < 4; nt++) {
        int r = br_ + nt * 8;
        bBase[nt] = (uint32_t)(r * 64);
        bSw[nt]   = (uint32_t)((r >> 1) & 3);
    }

    auto compute_stage = [&](int st) {
        uint32_t base = smem + st * STAGEB;
#pragma unroll
        for (int k16 = 0; k16 < 2; k16++) {
            uint32_t ua = ua0 + 2 * k16;
            uint32_t ub = ub0 + 2 * k16;
            uint32_t a[2][4], b[4][2];
#pragma unroll
            for (int nt = 0; nt < 4; nt++)
                LDSM2(b[nt], base + S_BH + bBase[nt] + ((ub ^ bSw[nt]) << 4));
            LDSM4(a[0], base + S_AH + aBase0 + ((ua ^ aSw0) << 4));
            LDSM4(a[1], base + S_AH + aBase1 + ((ua ^ aSw1) << 4));
#pragma unroll
            for (int mt = 0; mt < 2; mt++)
#pragma unroll
                for (int nt = 0; nt < 4; nt++) mma16816(acc[mt][nt], a[mt], b[nt]);
        }
    };

    load_stage(0, 0); CP_COMMIT();
    load_stage(1, 1); CP_COMMIT();
    load_stage(2, 2); CP_COMMIT();
    for (int kc = 0; kc < nchunks; kc++) {
        CP_WAIT2();
        __syncthreads();
        if (kc + 3 < nchunks) load_stage((kc + 3) & (NSTG - 1), kc + 3);
        CP_COMMIT();
        compute_stage(kc & (NSTG - 1));
    }

    // epilogue
#pragma unroll
    for (int mt = 0; mt < 2; mt++) {
        int r0 = m0 + wm * 32 + mt * 16 + (lane >> 2);
        int r1 = r0 + 8;
#pragma unroll
        for (int nt = 0; nt < 4; nt++) {
            int cc = n0 + wn * 32 + nt * 8 + (lane & 3) * 2;
            float b0 = bias[cc], b1 = bias[cc + 1];
            float v00 = acc[mt][nt][0] + b0, v01 = acc[mt][nt][1] + b1;
            float v10 = acc[mt][nt][2] + b0, v11 = acc[mt][nt][3] + b1;
            if (RELU) {
                v00 = fmaxf(v00, 0.f); v01 = fmaxf(v01, 0.f);
                v10 = fmaxf(v10, 0.f); v11 = fmaxf(v11, 0.f);
            }
            if (OUT == 0) {
                *(float2*)(cf + (size_t)r0 * ldc + cc) = make_float2(v00, v01);
                *(float2*)(cf + (size_t)r1 * ldc + cc) = make_float2(v10, v11);
            } else if (OUT == 1) {
                __half h00 = __float2half_rn(v00), h01 = __float2half_rn(v01);
                __half h10 = __float2half_rn(v10), h11 = __float2half_rn(v11);
                __half2 p0, p1, l0, l1;
                p0.x = h00; p0.y = h01; p1.x = h10; p1.y = h11;
                l0.x = __float2half_rn(v00 - __half2float(h00));
                l0.y = __float2half_rn(v01 - __half2float(h01));
                l1.x = __float2half_rn(v10 - __half2float(h10));
                l1.y = __float2half_rn(v11 - __half2float(h11));
                *(__half2*)(c_hi + (size_t)r0 * ldcb + cc) = p0;
                *(__half2*)(c_hi + (size_t)r1 * ldcb + cc) = p1;
                *(__half2*)(c_lo + (size_t)r0 * ldcb + cc) = l0;
                *(__half2*)(c_lo + (size_t)r1 * ldcb + cc) = l1;
            } else {
                *(__half2*)(c_hi + (size_t)r0 * ldcb + cc) = __floats2half2_rn(v00, v01);
                *(__half2*)(c_hi + (size_t)r1 * ldcb + cc) = __floats2half2_rn(v10, v11);
            }
        }
    }
}

// ---------------- GEMM wrappers ----------------
__global__ __launch_bounds__(256, 3)
void k_gemm_proj(const float* __restrict__ bf, const float* __restrict__ br,
                 const float* __restrict__ bm)
{
    int z = blockIdx.z;
    const __half* ah = g_inh + (size_t)z * NS;
    int off = (z == 0) ? OFF_WF : (z == 1) ? OFF_WR : OFF_WM;
    const float* bias = (z == 0) ? bf : (z == 1) ? br : bm;
    gemm_mma<0, 1>(ah, ah, ah, 512, 16, g_bwh + off, 512, bias,
                   nullptr, 0, g_ph + (size_t)z * NS, g_pl + (size_t)z * NS, 512);
}

__global__ __launch_bounds__(256, 3)
void k_gemm_qkv()
{
    int s = blockIdx.z;
    const __half* ah = g_ph + (size_t)s * NS;
    int n0 = blockIdx.x * 64;
    int w = n0 >> 9;  // 0=q, 1=k, 2=v
    __half* buf = (w == 0) ? g_q16 : (w == 1) ? g_k16 : g_v16;
    __half* oh = buf + (size_t)s * 512 - (size_t)w * 512;
    gemm_mma<0, 2>(ah, ah, ah, 512, 16, g_bwh + OFF_WQ, 512, g_bqkv,
                   nullptr, 0, oh, nullptr, 1536);
}

__global__ __launch_bounds__(256, 3)
void k_gemm_h(const float* __restrict__ ba1)
{
    gemm_mma<1, 0>(g_ph, g_ph + NS, g_ph + 2 * (size_t)NS,
                   512, 48, g_bwh + OFF_WA1, 1536, ba1,
                   g_h, 256, nullptr, nullptr, 0);
}

__global__ __launch_bounds__(256, 3)
void k_gemm_o(const float* __restrict__ bo)
{
    gemm_mma<0, 0>(g_chh, g_chh, g_chh, 512, 16,
                   g_bwh + OFF_WO, 512, bo, g_o, 512, nullptr, nullptr, 0);
}

__global__ __launch_bounds__(256, 3)
void k_gemm_gate(const float* __restrict__ bg)
{
    gemm_mma<0, 0>(g_w2h, g_w2h, g_w2h, 512, 16,
                   g_bwh + OFF_WG, 512, bg, g_gl, 512, nullptr, nullptr, 0);
}

// ---------------- prep kernels ----------------
__global__ __launch_bounds__(256)
void k_split3(const float* __restrict__ x0, const float* __restrict__ x1,
              const float* __restrict__ x2)
{
    int z = blockIdx.z;
    const float* x = (z == 0) ? x0 : (z == 1) ? x1 : x2;
    __half* h = g_inh + (size_t)z * NS;
    int i = blockIdx.x * 256 + threadIdx.x;
    float4 v = ((const float4*)x)[i];
    ((__half2*)h)[2 * i]     = __floats2half2_rn(v.x, v.y);
    ((__half2*)h)[2 * i + 1] = __floats2half2_rn(v.z, v.w);
}

__global__ __launch_bounds__(256)
void k_tw_all(const float* __restrict__ W0, const float* __restrict__ W1,
              const float* __restrict__ W2, const float* __restrict__ W3,
              const float* __restrict__ W4, const float* __restrict__ W5,
              const float* __restrict__ W6, const float* __restrict__ W7,
              const float* __restrict__ W8)
{
    int z = blockIdx.z;
    const float* W;
    int R, C, off;
    switch (z) {
        case 0: W = W0; R = 512;  C = 512; off = OFF_WF;  break;
        case 1: W = W1; R = 512;  C = 512; off = OFF_WR;  break;
        case 2: W = W2; R = 512;  C = 512; off = OFF_WM;  break;
        case 3: W = W3; R = 512;  C = 512; off = OFF_WQ;  break;
        case 4: W = W4; R = 512;  C = 512; off = OFF_WK;  break;
        case 5: W = W5; R = 512;  C = 512; off = OFF_WV;  break;
        case 6: W = W6; R = 512;  C = 512; off = OFF_WO;  break;
        case 7: W = W7; R = 512;  C = 512; off = OFF_WG;  break;
        default: W = W8; R = 1536; C = 256; off = OFF_WA1; break;
    }
    int bx = blockIdx.x * 32, by = blockIdx.y * 32;
    if (bx >= C || by >= R) return;
    __shared__ float t[32][33];
    int x = threadIdx.x & 31, y = (threadIdx.x >> 5) * 4;
#pragma unroll
    for (int j = 0; j < 4; j++) t[y + j][x] = W[(size_t)(by + y + j) * C + bx + x];
    __syncthreads();
    __half* oh = g_bwh + off;
#pragma unroll
    for (int j = 0; j < 4; j++) {
        int n = bx + y + j, k = by + x;
        oh[(size_t)n * R + k] = __float2half_rn(t[x][y + j]);
    }
}

__global__ void k_bias(const float* __restrict__ bq, const float* __restrict__ bk,
                       const float* __restrict__ bv)
{
    int z = blockIdx.x, i = threadIdx.x;
    const float* b = (z == 0) ? bq : (z == 1) ? bk : bv;
    g_bqkv[z * 512 + i] = b[i];
}

// ---------------- small fused kernels ----------------
__global__ __launch_bounds__(128)
void k_aw(const float* __restrict__ Wa2, const float* __restrict__ ba2)
{
    int row = blockIdx.x * 4 + (threadIdx.x >> 5);
    int l = threadIdx.x & 31;
    const float* hr = g_h + (size_t)row * 256;
    float a0 = 0.f, a1 = 0.f, a2 = 0.f;
#pragma unroll
    for (int i = l; i < 256; i += 32) {
        float hv = hr[i];
        a0 = fmaf(hv, Wa2[i * 3 + 0], a0);
        a1 = fmaf(hv, Wa2[i * 3 + 1], a1);
        a2 = fmaf(hv, Wa2[i * 3 + 2], a2);
    }
#pragma unroll
    for (int off = 16; off; off >>= 1) {
        a0 += __shfl_xor_sync(0xffffffffu, a0, off);
        a1 += __shfl_xor_sync(0xffffffffu, a1, off);
        a2 += __shfl_xor_sync(0xffffffffu, a2, off);
    }
    if (l == 0) {
        a0 += ba2[0]; a1 += ba2[1]; a2 += ba2[2];
        float mx = fmaxf(a0, fmaxf(a1, a2));
        float e0 = expf(a0 - mx), e1 = expf(a1 - mx), e2 = expf(a2 - mx);
        float inv = 1.f / (e0 + e1 + e2);
        g_aw[row * 3 + 0] = e0 * inv;
        g_aw[row * 3 + 1] = e1 * inv;
        g_aw[row * 3 + 2] = e2 * inv;
    }
}

__device__ __forceinline__ float4 ldh4(const __half* p)
{
    uint2 u = *(const uint2*)p;
    __half2 a = *(__half2*)&u.x, b = *(__half2*)&u.y;
    float2 fa = __half22float2(a), fb = __half22float2(b);
    return make_float4(fa.x, fa.y, fb.x, fb.y);
}
__device__ __forceinline__ float d4(float4 a, float4 b)
{ return a.x * b.x + a.y * b.y + a.z * b.z + a.w * b.w; }

__global__ __launch_bounds__(128)
void k_attn()
{
    int b = blockIdx.x;
    int h = threadIdx.x >> 5;
    int l = threadIdx.x & 31;
    size_t base = (size_t)b * 1536 + h * 128 + l * 4;
    float4 q0 = ldh4(&g_q16[base]);
    float4 q1 = ldh4(&g_q16[base + 512]);
    float4 q2 = ldh4(&g_q16[base + 1024]);
    float4 k0 = ldh4(&g_k16[base]);
    float4 k1 = ldh4(&g_k16[base + 512]);
    float4 k2 = ldh4(&g_k16[base + 1024]);
    float4 v0 = ldh4(&g_v16[base]);
    float4 v1 = ldh4(&g_v16[base + 512]);
    float4 v2 = ldh4(&g_v16[base + 1024]);

    float sc[3][3];
    sc[0][0] = d4(q0, k0); sc[0][1] = d4(q0, k1); sc[0][2] = d4(q0, k2);
    sc[1][0] = d4(q1, k0); sc[1][1] = d4(q1, k1); sc[1][2] = d4(q1, k2);
    sc[2][0] = d4(q2, k0); sc[2][1] = d4(q2, k1); sc[2][2] = d4(q2, k2);
#pragma unroll
    for (int qi = 0; qi < 3; qi++)
#pragma unroll
        for (int si = 0; si < 3; si++)
#pragma unroll
            for (int off = 16; off; off >>= 1)
                sc[qi][si] += __shfl_xor_sync(0xffffffffu, sc[qi][si], off);

    const float scale = 0.088388347648318447f;
#pragma unroll
    for (int qi = 0; qi < 3; qi++) {
        float s0 = sc[qi][0] * scale, s1 = sc[qi][1] * scale, s2 = sc[qi][2] * scale;
        float mx = fmaxf(s0, fmaxf(s1, s2));
        float e0 = expf(s0 - mx), e1 = expf(s1 - mx), e2 = expf(s2 - mx);
        float inv = 1.f / (e0 + e1 + e2);
        float a0 = e0 * inv, a1 = e1 * inv, a2 = e2 * inv;
        float4 c;
        c.x = a0 * v0.x + a1 * v1.x + a2 * v2.x;
        c.y = a0 * v0.y + a1 * v1.y + a2 * v2.y;
        c.z = a0 * v0.z + a1 * v1.z + a2 * v2.z;
        c.w = a0 * v0.w + a1 * v1.w + a2 * v2.w;
        size_t ob = base + (size_t)qi * 512;
        ((__half2*)&g_chh[ob])[0] = __floats2half2_rn(c.x, c.y);
        ((__half2*)&g_chh[ob])[1] = __floats2half2_rn(c.z, c.w);
    }
}

__device__ __forceinline__ void block_reduce2(float& s, float& q, float* ss, float* sq)
{
#pragma unroll
    for (int off = 16; off; off >>= 1) {
        s += __shfl_xor_sync(0xffffffffu, s, off);
        q += __shfl_xor_sync(0xffffffffu, q, off);
    }
    int w = threadIdx.x >> 5;
    if ((threadIdx.x & 31) == 0) { ss[w] = s; sq[w] = q; }
    __syncthreads();
    s = ss[0] + ss[1] + ss[2] + ss[3];
    q = sq[0] + sq[1] + sq[2] + sq[3];
    __syncthreads();
}

__device__ __forceinline__ float4 rec4(const __half* hp, const __half* lp)
{
    float4 h = ldh4(hp), l = ldh4(lp);
    return make_float4(h.x + l.x, h.y + l.y, h.z + l.z, h.w + l.w);
}

__global__ __launch_bounds__(128)
void k_post1(const float* __restrict__ gamma1, const float* __restrict__ beta1)
{
    __shared__ float ss[4], sq[4];
    int b = blockIdx.x;
    int d = threadIdx.x * 4;
    float aw0 = g_aw[b * 3 + 0], aw1 = g_aw[b * 3 + 1], aw2 = g_aw[b * 3 + 2];
    float4 gm = *(const float4*)&gamma1[d];
    float4 be = *(const float4*)&beta1[d];
    float4 wacc = make_float4(0.f, 0.f, 0.f, 0.f);
#pragma unroll
    for (int s = 0; s < 3; s++) {
        size_t px = (size_t)s * NS + (size_t)b * 512 + d;
        float4 xv = rec4(&g_ph[px], &g_pl[px]);
        float4 ov = *(const float4*)&g_o[((size_t)b * 3 + s) * 512 + d];
        float4 v;
        v.x = xv.x + ov.x; v.y = xv.y + ov.y; v.z = xv.z + ov.z; v.w = xv.w + ov.w;
        float lsum = v.x + v.y + v.z + v.w;
        float lsq  = v.x * v.x + v.y * v.y + v.z * v.z + v.w * v.w;
        block_reduce2(lsum, lsq, ss, sq);
        float mean = lsum * (1.f / 512.f);
        float var  = lsq * (1.f / 512.f) - mean * mean;
        float inv  = rsqrtf(var + EPSLN);
        float a = (s == 0) ? aw0 : (s == 1) ? aw1 : aw2;
        wacc.x += a * (gm.x * (v.x - mean) * inv + be.x);
        wacc.y += a * (gm.y * (v.y - mean) * inv + be.y);
        wacc.z += a * (gm.z * (v.z - mean) * inv + be.z);
        wacc.w += a * (gm.w * (v.w - mean) * inv + be.w);
    }
    size_t ob = (size_t)b * 512 + d;
    *(float4*)&g_wt[ob] = wacc;
    ((__half2*)&g_w2h[ob])[0] = __floats2half2_rn(wacc.x, wacc.y);
    ((__half2*)&g_w2h[ob])[1] = __floats2half2_rn(wacc.z, wacc.w);
}

__device__ __forceinline__ float sigm(float x) { return 1.f / (1.f + expf(-x)); }

__global__ __launch_bounds__(128)
void k_post2(const float* __restrict__ gamma2, const float* __restrict__ beta2,
             float* __restrict__ out)
{
    __shared__ float ss[4], sq[4];
    int b = blockIdx.x;
    int d = threadIdx.x * 4;
    size_t ob = (size_t)b * 512 + d;
    float4 wv = *(const float4*)&g_wt[ob];
    float4 gl = *(const float4*)&g_gl[ob];
    size_t pm = 2 * (size_t)NS + ob;
    float4 mp = rec4(&g_ph[pm], &g_pl[pm]);
    float4 t;
    t.x = mp.x + sigm(gl.x) * wv.x;
    t.y = mp.y + sigm(gl.y) * wv.y;
    t.z = mp.z + sigm(gl.z) * wv.z;
    t.w = mp.w + sigm(gl.w) * wv.w;
    float lsum = t.x + t.y + t.z + t.w;
    float lsq  = t.x * t.x + t.y * t.y + t.z * t.z + t.w * t.w;
    block_reduce2(lsum, lsq, ss, sq);
    float mean = lsum * (1.f / 512.f);
    float var  = lsq * (1.f / 512.f) - mean * mean;
    float inv  = rsqrtf(var + EPSLN);
    float4 gm = *(const float4*)&gamma2[d];
    float4 be = *(const float4*)&beta2[d];
    float4 r;
    r.x = gm.x * (t.x - mean) * inv + be.x;
    r.y = gm.y * (t.y - mean) * inv + be.y;
    r.z = gm.z * (t.z - mean) * inv + be.z;
    r.w = gm.w * (t.w - mean) * inv + be.w;
    *(float4*)&out[ob] = r;
}

// ---------------- launch ----------------
extern "C" void kernel_launch(void* const* d_in, const int* in_sizes, int n_in,
                              void* d_out, int out_size)
{
    const float* frontier = (const float*)d_in[0];
    const float* cross    = (const float*)d_in[1];
    const float* mapf     = (const float*)d_in[2];
    const float* Wf  = (const float*)d_in[3];
    const float* bf  = (const float*)d_in[4];
    const float* Wr  = (const float*)d_in[5];
    const float* br  = (const float*)d_in[6];
    const float* Wm  = (const float*)d_in[7];
    const float* bm  = (const float*)d_in[8];
    const float* Wa1 = (const float*)d_in[9];
    const float* ba1 = (const float*)d_in[10];
    const float* Wa2 = (const float*)d_in[11];
    const float* ba2 = (const float*)d_in[12];
    const float* Wq  = (const float*)d_in[13];
    const float* bq  = (const float*)d_in[14];
    const float* Wk  = (const float*)d_in[15];
    const float* bk  = (const float*)d_in[16];
    const float* Wv  = (const float*)d_in[17];
    const float* bv  = (const float*)d_in[18];
    const float* Wo  = (const float*)d_in[19];
    const float* bo  = (const float*)d_in[20];
    const float* Wg  = (const float*)d_in[21];
    const float* bg  = (const float*)d_in[22];
    const float* gamma1 = (const float*)d_in[23];
    const float* beta1  = (const float*)d_in[24];
    const float* gamma2 = (const float*)d_in[25];
    const float* beta2  = (const float*)d_in[26];

    static int inited = 0;
    static cudaStream_t s1;
    static cudaEvent_t evFork, evPrep, evProj, evAw;
    if (!inited) {
        cudaFuncSetAttribute(k_gemm_proj, cudaFuncAttributeMaxDynamicSharedMemorySize, NSTG * STAGEB);
        cudaFuncSetAttribute(k_gemm_qkv,  cudaFuncAttributeMaxDynamicSharedMemorySize, NSTG * STAGEB);
        cudaFuncSetAttribute(k_gemm_h,    cudaFuncAttributeMaxDynamicSharedMemorySize, NSTG * STAGEB);
        cudaFuncSetAttribute(k_gemm_o,    cudaFuncAttributeMaxDynamicSharedMemorySize, NSTG * STAGEB);
        cudaFuncSetAttribute(k_gemm_gate, cudaFuncAttributeMaxDynamicSharedMemorySize, NSTG * STAGEB);
        cudaStreamCreateWithFlags(&s1, cudaStreamNonBlocking);
        cudaEventCreateWithFlags(&evFork, cudaEventDisableTiming);
        cudaEventCreateWithFlags(&evPrep, cudaEventDisableTiming);
        cudaEventCreateWithFlags(&evProj, cudaEventDisableTiming);
        cudaEventCreateWithFlags(&evAw,   cudaEventDisableTiming);
        inited = 1;
    }

    // fork: weight prep on s1, input split on default stream
    cudaEventRecord(evFork, 0);
    cudaStreamWaitEvent(s1, evFork, 0);
    k_tw_all<<<dim3(16, 48, 9), 256, 0, s1>>>(Wf, Wr, Wm, Wq, Wk, Wv, Wo, Wg, Wa1);
    k_bias<<<3, 512, 0, s1>>>(bq, bk, bv);
    cudaEventRecord(evPrep, s1);

    k_split3<<<dim3(8192, 1, 3), 256>>>(frontier, cross, mapf);
    cudaStreamWaitEvent(0, evPrep, 0);

    k_gemm_proj<<<dim3(8, 128, 3), 256, NSTG * STAGEB>>>(bf, br, bm);
    cudaEventRecord(evProj, 0);

    // branch A (s1): h -> aw
    cudaStreamWaitEvent(s1, evProj, 0);
    k_gemm_h<<<dim3(4, 128, 1), 256, NSTG * STAGEB, s1>>>(ba1);
    k_aw<<<BSZ / 4, 128, 0, s1>>>(Wa2, ba2);
    cudaEventRecord(evAw, s1);

    // branch B (default): qkv -> attn -> o
    k_gemm_qkv<<<dim3(24, 128, 3), 256, NSTG * STAGEB>>>();
    k_attn<<<BSZ, 128>>>();
    k_gemm_o<<<dim3(8, 384, 1), 256, NSTG * STAGEB>>>(bo);

    // join
    cudaStreamWaitEvent(0, evAw, 0);
    k_post1<<<BSZ, 128>>>(gamma1, beta1);
    k_gemm_gate<<<dim3(8, 128, 1), 256, NSTG * STAGEB>>>(bg);
    k_post2<<<BSZ, 128>>>(gamma2, beta2, (float*)d_out);
}

// round 14
// speedup vs baseline: 1.0495x; 1.0061x over previous
#include <cuda_runtime.h>
#include <cuda_fp16.h>
#include <stdint.h>
#include <math.h>

#define BSZ 16384
#define DM  512
#define NS  (BSZ*DM)
#define EPSLN 1e-6f

// ---------------- device-global scratch ----------------
__device__ __half g_inh[3*NS];                 // input hi
__device__ __half g_ph [3*NS], g_pl [3*NS];    // proj hi/lo (lo for exact residual)
__device__ __half g_chh[3*NS];                 // ctx hi (rows = B*3)
__device__ __half g_w2h[NS];                   // weighted hi
__device__ __half g_q16[3*NS], g_k16[3*NS], g_v16[3*NS];  // [B,3,512] fp16
__device__ __half g_o16[3*NS];                 // attention output (fp16)
__device__ __half g_gl16[NS];                  // gate logits (fp16)
// transposed fp16 weights ([N,K] row-major); WQ/WK/WV contiguous
#define OFF_WF  0
#define OFF_WR  262144
#define OFF_WM  524288
#define OFF_WQ  786432
#define OFF_WK  1048576
#define OFF_WV  1310720
#define OFF_WO  1572864
#define OFF_WG  1835008
#define OFF_WA1 2097152
#define WT_TOTAL (2097152 + 393216)
__device__ __half g_bwh[WT_TOTAL];
__device__ float g_bqkv[1536];
// fp32 scratch
__device__ float g_h [BSZ*256];
__device__ float g_aw[BSZ*3];
__device__ float g_wt[NS];

// ---------------- PTX helpers ----------------
__device__ __forceinline__ uint32_t smem_u32(const void* p) {
    uint32_t a;
    asm("{ .reg .u64 t; cvta.to.shared.u64 t, %1; cvt.u32.u64 %0, t; }" : "=r"(a) : "l"(p));
    return a;
}
#define CP16(sm, gp) \
    asm volatile("cp.async.cg.shared.global [%0], [%1], 16;" :: "r"(sm), "l"(gp) : "memory")
#define CP_COMMIT() asm volatile("cp.async.commit_group;" ::: "memory")
#define CP_WAIT2()  asm volatile("cp.async.wait_group 2;" ::: "memory")
#define LDSM4(d, a) \
    asm volatile("ldmatrix.sync.aligned.m8n8.x4.shared.b16 {%0,%1,%2,%3}, [%4];" \
        : "=r"((d)[0]), "=r"((d)[1]), "=r"((d)[2]), "=r"((d)[3]) : "r"(a))
#define LDSM2(d, a) \
    asm volatile("ldmatrix.sync.aligned.m8n8.x2.shared.b16 {%0,%1}, [%2];" \
        : "=r"((d)[0]), "=r"((d)[1]) : "r"(a))
__device__ __forceinline__ void mma16816(float* c, const uint32_t* a, const uint32_t* b) {
    asm volatile("mma.sync.aligned.m16n8k16.row.col.f32.f16.f16.f32 "
        "{%0,%1,%2,%3}, {%4,%5,%6,%7}, {%8,%9}, {%0,%1,%2,%3};"
        : "+f"(c[0]), "+f"(c[1]), "+f"(c[2]), "+f"(c[3])
        : "r"(a[0]), "r"(a[1]), "r"(a[2]), "r"(a[3]), "r"(b[0]), "r"(b[1]));
}

// ---------------- pure fp16 GEMM: tile 128x64x32, 256 thr, warp 32x32 ----------
// (R9 core: proven local optimum; unchanged)
#define S_AH   0
#define S_BH   8192
#define STAGEB 12288
#define NSTG   4
__device__ __forceinline__ uint32_t swz(int row, int u) {
    return (uint32_t)(row * 64 + ((u ^ ((row >> 1) & 3)) << 4));
}
// OUT: 0 = fp32, 1 = fp16 hi/lo, 2 = fp16 hi only

template <int RELU, int OUT>
__device__ __forceinline__ void gemm_mma(
    const __half* __restrict__ a_h0, const __half* __restrict__ a_h1,
    const __half* __restrict__ a_h2,
    int lda, int nchunks,
    const __half* __restrict__ b_h, int ldb,
    const float* __restrict__ bias,
    float* __restrict__ cf, int ldc,
    __half* __restrict__ c_hi, __half* __restrict__ c_lo, int ldcb)
{
    extern __shared__ char dsm[];
    const uint32_t smem = smem_u32(dsm);
    const int tid  = threadIdx.x;
    const int lane = tid & 31;
    const int warp = tid >> 5;
    const int wm = warp & 3;
    const int wn = warp >> 2;
    const int m0 = blockIdx.y * 128;
    const int n0 = blockIdx.x * 64;

    float acc[2][4][4];
#pragma unroll
    for (int i = 0; i < 2; i++)
#pragma unroll
        for (int j = 0; j < 4; j++)
#pragma unroll
            for (int k = 0; k < 4; k++) acc[i][j][k] = 0.f;

    const int arow = tid >> 1;
    const int au   = (tid & 1) * 2;
    const int brow = tid >> 2;
    const int bu   = tid & 3;
    const uint32_t aswz0 = swz(arow, au);
    const uint32_t aswz1 = swz(arow, au + 1);
    const uint32_t bswz  = swz(brow, bu);

    auto load_stage = [&](int st, int kc) {
        int seg = kc >> 4;
        const __half* ah = (seg == 0) ? a_h0 : (seg == 1) ? a_h1 : a_h2;
        size_t abase = (size_t)(m0 + arow) * lda + (kc & 15) * 32;
        uint32_t sb = smem + st * STAGEB;
        CP16(sb + S_AH + aswz0, ah + abase + au * 8);
        CP16(sb + S_AH + aswz1, ah + abase + au * 8 + 8);
        CP16(sb + S_BH + bswz, b_h + (size_t)(n0 + brow) * ldb + kc * 32 + bu * 8);
    };

    int ar0 = wm * 32 + (lane & 15);
    int ar1 = ar0 + 16;
    const uint32_t aBase0 = (uint32_t)(ar0 * 64), aSw0 = (uint32_t)((ar0 >> 1) & 3);
    const uint32_t aBase1 = (uint32_t)(ar1 * 64), aSw1 = (uint32_t)((ar1 >> 1) & 3);
    const uint32_t ua0 = (uint32_t)(lane >> 4);
    int br_ = wn * 32 + (lane & 7);
    const uint32_t ub0 = (uint32_t)((lane >> 3) & 1);
    uint32_t bBase[4], bSw[4];
#pragma unroll
    for (int nt = 0; nt < 4; nt++) {
        int r = br_ + nt * 8;
        bBase[nt] = (uint32_t)(r * 64);
        bSw[nt]   = (uint32_t)((r >> 1) & 3);
    }

    auto compute_stage = [&](int st) {
        uint32_t base = smem + st * STAGEB;
#pragma unroll
        for (int k16 = 0; k16 < 2; k16++) {
            uint32_t ua = ua0 + 2 * k16;
            uint32_t ub = ub0 + 2 * k16;
            uint32_t a[2][4], b[4][2];
#pragma unroll
            for (int nt = 0; nt < 4; nt++)
                LDSM2(b[nt], base + S_BH + bBase[nt] + ((ub ^ bSw[nt]) << 4));
            LDSM4(a[0], base + S_AH + aBase0 + ((ua ^ aSw0) << 4));
            LDSM4(a[1], base + S_AH + aBase1 + ((ua ^ aSw1) << 4));
#pragma unroll
            for (int mt = 0; mt < 2; mt++)
#pragma unroll
                for (int nt = 0; nt < 4; nt++) mma16816(acc[mt][nt], a[mt], b[nt]);
        }
    };

    load_stage(0, 0); CP_COMMIT();
    load_stage(1, 1); CP_COMMIT();
    load_stage(2, 2); CP_COMMIT();
    for (int kc = 0; kc < nchunks; kc++) {
        CP_WAIT2();
        __syncthreads();
        if (kc + 3 < nchunks) load_stage((kc + 3) & (NSTG - 1), kc + 3);
        CP_COMMIT();
        compute_stage(kc & (NSTG - 1));
    }

    // epilogue
#pragma unroll
    for (int mt = 0; mt < 2; mt++) {
        int r0 = m0 + wm * 32 + mt * 16 + (lane >> 2);
        int r1 = r0 + 8;
#pragma unroll
        for (int nt = 0; nt < 4; nt++) {
            int cc = n0 + wn * 32 + nt * 8 + (lane & 3) * 2;
            float b0 = bias[cc], b1 = bias[cc + 1];
            float v00 = acc[mt][nt][0] + b0, v01 = acc[mt][nt][1] + b1;
            float v10 = acc[mt][nt][2] + b0, v11 = acc[mt][nt][3] + b1;
            if (RELU) {
                v00 = fmaxf(v00, 0.f); v01 = fmaxf(v01, 0.f);
                v10 = fmaxf(v10, 0.f); v11 = fmaxf(v11, 0.f);
            }
            if (OUT == 0) {
                *(float2*)(cf + (size_t)r0 * ldc + cc) = make_float2(v00, v01);
                *(float2*)(cf + (size_t)r1 * ldc + cc) = make_float2(v10, v11);
            } else if (OUT == 1) {
                __half h00 = __float2half_rn(v00), h01 = __float2half_rn(v01);
                __half h10 = __float2half_rn(v10), h11 = __float2half_rn(v11);
                __half2 p0, p1, l0, l1;
                p0.x = h00; p0.y = h01; p1.x = h10; p1.y = h11;
                l0.x = __float2half_rn(v00 - __half2float(h00));
                l0.y = __float2half_rn(v01 - __half2float(h01));
                l1.x = __float2half_rn(v10 - __half2float(h10));
                l1.y = __float2half_rn(v11 - __half2float(h11));
                *(__half2*)(c_hi + (size_t)r0 * ldcb + cc) = p0;
                *(__half2*)(c_hi + (size_t)r1 * ldcb + cc) = p1;
                *(__half2*)(c_lo + (size_t)r0 * ldcb + cc) = l0;
                *(__half2*)(c_lo + (size_t)r1 * ldcb + cc) = l1;
            } else {
                *(__half2*)(c_hi + (size_t)r0 * ldcb + cc) = __floats2half2_rn(v00, v01);
                *(__half2*)(c_hi + (size_t)r1 * ldcb + cc) = __floats2half2_rn(v10, v11);
            }
        }
    }
}

// ---------------- GEMM wrappers ----------------
__global__ __launch_bounds__(256, 3)
void k_gemm_proj1(int z, const float* __restrict__ bias)
{
    const __half* ah = g_inh + (size_t)z * NS;
    int off = (z == 0) ? OFF_WF : (z == 1) ? OFF_WR : OFF_WM;
    gemm_mma<0, 1>(ah, ah, ah, 512, 16, g_bwh + off, 512, bias,
                   nullptr, 0, g_ph + (size_t)z * NS, g_pl + (size_t)z * NS, 512);
}

__global__ __launch_bounds__(256, 3)
void k_gemm_qkv()
{
    int s = blockIdx.z;
    const __half* ah = g_ph + (size_t)s * NS;
    int n0 = blockIdx.x * 64;
    int w = n0 >> 9;  // 0=q, 1=k, 2=v
    __half* buf = (w == 0) ? g_q16 : (w == 1) ? g_k16 : g_v16;
    __half* oh = buf + (size_t)s * 512 - (size_t)w * 512;
    gemm_mma<0, 2>(ah, ah, ah, 512, 16, g_bwh + OFF_WQ, 512, g_bqkv,
                   nullptr, 0, oh, nullptr, 1536);
}

__global__ __launch_bounds__(256, 3)
void k_gemm_h(const float* __restrict__ ba1)
{
    gemm_mma<1, 0>(g_ph, g_ph + NS, g_ph + 2 * (size_t)NS,
                   512, 48, g_bwh + OFF_WA1, 1536, ba1,
                   g_h, 256, nullptr, nullptr, 0);
}

__global__ __launch_bounds__(256, 3)
void k_gemm_o(const float* __restrict__ bo)
{
    gemm_mma<0, 2>(g_chh, g_chh, g_chh, 512, 16,
                   g_bwh + OFF_WO, 512, bo, nullptr, 0, g_o16, nullptr, 512);
}

__global__ __launch_bounds__(256, 3)
void k_gemm_gate(const float* __restrict__ bg)
{
    gemm_mma<0, 2>(g_w2h, g_w2h, g_w2h, 512, 16,
                   g_bwh + OFF_WG, 512, bg, nullptr, 0, g_gl16, nullptr, 512);
}

// ---------------- prep kernels ----------------
__global__ __launch_bounds__(256)
void k_split1(const float* __restrict__ x, int z)
{
    __half* h = g_inh + (size_t)z * NS;
    int i = blockIdx.x * 256 + threadIdx.x;
    float4 v = ((const float4*)x)[i];
    ((__half2*)h)[2 * i]     = __floats2half2_rn(v.x, v.y);
    ((__half2*)h)[2 * i + 1] = __floats2half2_rn(v.z, v.w);
}

__global__ __launch_bounds__(256)
void k_tw_all(const float* __restrict__ W0, const float* __restrict__ W1,
              const float* __restrict__ W2, const float* __restrict__ W3,
              const float* __restrict__ W4, const float* __restrict__ W5,
              const float* __restrict__ W6, const float* __restrict__ W7,
              const float* __restrict__ W8)
{
    int z = blockIdx.z;
    const float* W;
    int R, C, off;
    switch (z) {
        case 0: W = W0; R = 512;  C = 512; off = OFF_WF;  break;
        case 1: W = W1; R = 512;  C = 512; off = OFF_WR;  break;
        case 2: W = W2; R = 512;  C = 512; off = OFF_WM;  break;
        case 3: W = W3; R = 512;  C = 512; off = OFF_WQ;  break;
        case 4: W = W4; R = 512;  C = 512; off = OFF_WK;  break;
        case 5: W = W5; R = 512;  C = 512; off = OFF_WV;  break;
        case 6: W = W6; R = 512;  C = 512; off = OFF_WO;  break;
        case 7: W = W7; R = 512;  C = 512; off = OFF_WG;  break;
        default: W = W8; R = 1536; C = 256; off = OFF_WA1; break;
    }
    int bx = blockIdx.x * 32, by = blockIdx.y * 32;
    if (bx >= C || by >= R) return;
    __shared__ float t[32][33];
    int x = threadIdx.x & 31, y = (threadIdx.x >> 5) * 4;
#pragma unroll
    for (int j = 0; j < 4; j++) t[y + j][x] = W[(size_t)(by + y + j) * C + bx + x];
    __syncthreads();
    __half* oh = g_bwh + off;
#pragma unroll
    for (int j = 0; j < 4; j++) {
        int n = bx + y + j, k = by + x;
        oh[(size_t)n * R + k] = __float2half_rn(t[x][y + j]);
    }
}

__global__ void k_bias(const float* __restrict__ bq, const float* __restrict__ bk,
                       const float* __restrict__ bv)
{
    int z = blockIdx.x, i = threadIdx.x;
    const float* b = (z == 0) ? bq : (z == 1) ? bk : bv;
    g_bqkv[z * 512 + i] = b[i];
}

// ---------------- small fused kernels ----------------
__global__ __launch_bounds__(128)
void k_aw(const float* __restrict__ Wa2, const float* __restrict__ ba2)
{
    int row = blockIdx.x * 4 + (threadIdx.x >> 5);
    int l = threadIdx.x & 31;
    const float* hr = g_h + (size_t)row * 256;
    float a0 = 0.f, a1 = 0.f, a2 = 0.f;
#pragma unroll
    for (int i = l; i < 256; i += 32) {
        float hv = hr[i];
        a0 = fmaf(hv, Wa2[i * 3 + 0], a0);
        a1 = fmaf(hv, Wa2[i * 3 + 1], a1);
        a2 = fmaf(hv, Wa2[i * 3 + 2], a2);
    }
#pragma unroll
    for (int off = 16; off; off >>= 1) {
        a0 += __shfl_xor_sync(0xffffffffu, a0, off);
        a1 += __shfl_xor_sync(0xffffffffu, a1, off);
        a2 += __shfl_xor_sync(0xffffffffu, a2, off);
    }
    if (l == 0) {
        a0 += ba2[0]; a1 += ba2[1]; a2 += ba2[2];
        float mx = fmaxf(a0, fmaxf(a1, a2));
        float e0 = expf(a0 - mx), e1 = expf(a1 - mx), e2 = expf(a2 - mx);
        float inv = 1.f / (e0 + e1 + e2);
        g_aw[row * 3 + 0] = e0 * inv;
        g_aw[row * 3 + 1] = e1 * inv;
        g_aw[row * 3 + 2] = e2 * inv;
    }
}

__device__ __forceinline__ float4 ldh4(const __half* p)
{
    uint2 u = *(const uint2*)p;
    __half2 a = *(__half2*)&u.x, b = *(__half2*)&u.y;
    float2 fa = __half22float2(a), fb = __half22float2(b);
    return make_float4(fa.x, fa.y, fb.x, fb.y);
}
__device__ __forceinline__ float d4(float4 a, float4 b)
{ return a.x * b.x + a.y * b.y + a.z * b.z + a.w * b.w; }

__global__ __launch_bounds__(128)
void k_attn()
{
    int b = blockIdx.x;
    int h = threadIdx.x >> 5;
    int l = threadIdx.x & 31;
    size_t base = (size_t)b * 1536 + h * 128 + l * 4;
    float4 q0 = ldh4(&g_q16[base]);
    float4 q1 = ldh4(&g_q16[base + 512]);
    float4 q2 = ldh4(&g_q16[base + 1024]);
    float4 k0 = ldh4(&g_k16[base]);
    float4 k1 = ldh4(&g_k16[base + 512]);
    float4 k2 = ldh4(&g_k16[base + 1024]);
    float4 v0 = ldh4(&g_v16[base]);
    float4 v1 = ldh4(&g_v16[base + 512]);
    float4 v2 = ldh4(&g_v16[base + 1024]);

    float sc[3][3];
    sc[0][0] = d4(q0, k0); sc[0][1] = d4(q0, k1); sc[0][2] = d4(q0, k2);
    sc[1][0] = d4(q1, k0); sc[1][1] = d4(q1, k1); sc[1][2] = d4(q1, k2);
    sc[2][0] = d4(q2, k0); sc[2][1] = d4(q2, k1); sc[2][2] = d4(q2, k2);
#pragma unroll
    for (int qi = 0; qi < 3; qi++)
#pragma unroll
        for (int si = 0; si < 3; si++)
#pragma unroll
            for (int off = 16; off; off >>= 1)
                sc[qi][si] += __shfl_xor_sync(0xffffffffu, sc[qi][si], off);

    const float scale = 0.088388347648318447f;
#pragma unroll
    for (int qi = 0; qi < 3; qi++) {
        float s0 = sc[qi][0] * scale, s1 = sc[qi][1] * scale, s2 = sc[qi][2] * scale;
        float mx = fmaxf(s0, fmaxf(s1, s2));
        float e0 = expf(s0 - mx), e1 = expf(s1 - mx), e2 = expf(s2 - mx);
        float inv = 1.f / (e0 + e1 + e2);
        float a0 = e0 * inv, a1 = e1 * inv, a2 = e2 * inv;
        float4 c;
        c.x = a0 * v0.x + a1 * v1.x + a2 * v2.x;
        c.y = a0 * v0.y + a1 * v1.y + a2 * v2.y;
        c.z = a0 * v0.z + a1 * v1.z + a2 * v2.z;
        c.w = a0 * v0.w + a1 * v1.w + a2 * v2.w;
        size_t ob = base + (size_t)qi * 512;
        ((__half2*)&g_chh[ob])[0] = __floats2half2_rn(c.x, c.y);
        ((__half2*)&g_chh[ob])[1] = __floats2half2_rn(c.z, c.w);
    }
}

__device__ __forceinline__ void block_reduce2(float& s, float& q, float* ss, float* sq)
{
#pragma unroll
    for (int off = 16; off; off >>= 1) {
        s += __shfl_xor_sync(0xffffffffu, s, off);
        q += __shfl_xor_sync(0xffffffffu, q, off);
    }
    int w = threadIdx.x >> 5;
    if ((threadIdx.x & 31) == 0) { ss[w] = s; sq[w] = q; }
    __syncthreads();
    s = ss[0] + ss[1] + ss[2] + ss[3];
    q = sq[0] + sq[1] + sq[2] + sq[3];
    __syncthreads();
}

__device__ __forceinline__ float4 rec4(const __half* hp, const __half* lp)
{
    float4 h = ldh4(hp), l = ldh4(lp);
    return make_float4(h.x + l.x, h.y + l.y, h.z + l.z, h.w + l.w);
}

__global__ __launch_bounds__(128)
void k_post1(const float* __restrict__ gamma1, const float* __restrict__ beta1)
{
    __shared__ float ss[4], sq[4];
    int b = blockIdx.x;
    int d = threadIdx.x * 4;
    float aw0 = g_aw[b * 3 + 0], aw1 = g_aw[b * 3 + 1], aw2 = g_aw[b * 3 + 2];
    float4 gm = *(const float4*)&gamma1[d];
    float4 be = *(const float4*)&beta1[d];
    float4 wacc = make_float4(0.f, 0.f, 0.f, 0.f);
#pragma unroll
    for (int s = 0; s < 3; s++) {
        size_t px = (size_t)s * NS + (size_t)b * 512 + d;
        float4 xv = rec4(&g_ph[px], &g_pl[px]);
        float4 ov = ldh4(&g_o16[((size_t)b * 3 + s) * 512 + d]);
        float4 v;
        v.x = xv.x + ov.x; v.y = xv.y + ov.y; v.z = xv.z + ov.z; v.w = xv.w + ov.w;
        float lsum = v.x + v.y + v.z + v.w;
        float lsq  = v.x * v.x + v.y * v.y + v.z * v.z + v.w * v.w;
        block_reduce2(lsum, lsq, ss, sq);
        float mean = lsum * (1.f / 512.f);
        float var  = lsq * (1.f / 512.f) - mean * mean;
        float inv  = rsqrtf(var + EPSLN);
        float a = (s == 0) ? aw0 : (s == 1) ? aw1 : aw2;
        wacc.x += a * (gm.x * (v.x - mean) * inv + be.x);
        wacc.y += a * (gm.y * (v.y - mean) * inv + be.y);
        wacc.z += a * (gm.z * (v.z - mean) * inv + be.z);
        wacc.w += a * (gm.w * (v.w - mean) * inv + be.w);
    }
    size_t ob = (size_t)b * 512 + d;
    *(float4*)&g_wt[ob] = wacc;
    ((__half2*)&g_w2h[ob])[0] = __floats2half2_rn(wacc.x, wacc.y);
    ((__half2*)&g_w2h[ob])[1] = __floats2half2_rn(wacc.z, wacc.w);
}

__device__ __forceinline__ float sigm(float x) { return 1.f / (1.f + expf(-x)); }

__global__ __launch_bounds__(128)
void k_post2(const float* __restrict__ gamma2, const float* __restrict__ beta2,
             float* __restrict__ out)
{
    __shared__ float ss[4], sq[4];
    int b = blockIdx.x;
    int d = threadIdx.x * 4;
    size_t ob = (size_t)b * 512 + d;
    float4 wv = *(const float4*)&g_wt[ob];
    float4 gl = ldh4(&g_gl16[ob]);
    size_t pm = 2 * (size_t)NS + ob;
    float4 mp = rec4(&g_ph[pm], &g_pl[pm]);
    float4 t;
    t.x = mp.x + sigm(gl.x) * wv.x;
    t.y = mp.y + sigm(gl.y) * wv.y;
    t.z = mp.z + sigm(gl.z) * wv.z;
    t.w = mp.w + sigm(gl.w) * wv.w;
    float lsum = t.x + t.y + t.z + t.w;
    float lsq  = t.x * t.x + t.y * t.y + t.z * t.z + t.w * t.w;
    block_reduce2(lsum, lsq, ss, sq);
    float mean = lsum * (1.f / 512.f);
    float var  = lsq * (1.f / 512.f) - mean * mean;
    float inv  = rsqrtf(var + EPSLN);
    float4 gm = *(const float4*)&gamma2[d];
    float4 be = *(const float4*)&beta2[d];
    float4 r;
    r.x = gm.x * (t.x - mean) * inv + be.x;
    r.y = gm.y * (t.y - mean) * inv + be.y;
    r.z = gm.z * (t.z - mean) * inv + be.z;
    r.w = gm.w * (t.w - mean) * inv + be.w;
    *(float4*)&out[ob] = r;
}

// ---------------- launch ----------------
extern "C" void kernel_launch(void* const* d_in, const int* in_sizes, int n_in,
                              void* d_out, int out_size)
{
    const float* frontier = (const float*)d_in[0];
    const float* cross    = (const float*)d_in[1];
    const float* mapf     = (const float*)d_in[2];
    const float* Wf  = (const float*)d_in[3];
    const float* bf  = (const float*)d_in[4];
    const float* Wr  = (const float*)d_in[5];
    const float* br  = (const float*)d_in[6];
    const float* Wm  = (const float*)d_in[7];
    const float* bm  = (const float*)d_in[8];
    const float* Wa1 = (const float*)d_in[9];
    const float* ba1 = (const float*)d_in[10];
    const float* Wa2 = (const float*)d_in[11];
    const float* ba2 = (const float*)d_in[12];
    const float* Wq  = (const float*)d_in[13];
    const float* bq  = (const float*)d_in[14];
    const float* Wk  = (const float*)d_in[15];
    const float* bk  = (const float*)d_in[16];
    const float* Wv  = (const float*)d_in[17];
    const float* bv  = (const float*)d_in[18];
    const float* Wo  = (const float*)d_in[19];
    const float* bo  = (const float*)d_in[20];
    const float* Wg  = (const float*)d_in[21];
    const float* bg  = (const float*)d_in[22];
    const float* gamma1 = (const float*)d_in[23];
    const float* beta1  = (const float*)d_in[24];
    const float* gamma2 = (const float*)d_in[25];
    const float* beta2  = (const float*)d_in[26];

    static int inited = 0;
    static cudaStream_t s1;
    static cudaEvent_t evFork, evPrep, evS0, evS1, evP01, evProj, evAw;
    if (!inited) {
        cudaFuncSetAttribute(k_gemm_proj1, cudaFuncAttributeMaxDynamicSharedMemorySize, NSTG * STAGEB);
        cudaFuncSetAttribute(k_gemm_qkv,   cudaFuncAttributeMaxDynamicSharedMemorySize, NSTG * STAGEB);
        cudaFuncSetAttribute(k_gemm_h,     cudaFuncAttributeMaxDynamicSharedMemorySize, NSTG * STAGEB);
        cudaFuncSetAttribute(k_gemm_o,     cudaFuncAttributeMaxDynamicSharedMemorySize, NSTG * STAGEB);
        cudaFuncSetAttribute(k_gemm_gate,  cudaFuncAttributeMaxDynamicSharedMemorySize, NSTG * STAGEB);
        cudaStreamCreateWithFlags(&s1, cudaStreamNonBlocking);
        cudaEventCreateWithFlags(&evFork, cudaEventDisableTiming);
        cudaEventCreateWithFlags(&evPrep, cudaEventDisableTiming);
        cudaEventCreateWithFlags(&evS0,   cudaEventDisableTiming);
        cudaEventCreateWithFlags(&evS1,   cudaEventDisableTiming);
        cudaEventCreateWithFlags(&evP01,  cudaEventDisableTiming);
        cudaEventCreateWithFlags(&evProj, cudaEventDisableTiming);
        cudaEventCreateWithFlags(&evAw,   cudaEventDisableTiming);
        inited = 1;
    }

    // fork: weight prep on s1; input splits on default
    cudaEventRecord(evFork, 0);
    cudaStreamWaitEvent(s1, evFork, 0);
    k_tw_all<<<dim3(16, 48, 9), 256, 0, s1>>>(Wf, Wr, Wm, Wq, Wk, Wv, Wo, Wg, Wa1);
    k_bias<<<3, 512, 0, s1>>>(bq, bk, bv);
    cudaEventRecord(evPrep, s1);

    k_split1<<<8192, 256>>>(frontier, 0);
    cudaEventRecord(evS0, 0);
    k_split1<<<8192, 256>>>(cross, 1);
    cudaEventRecord(evS1, 0);
    k_split1<<<8192, 256>>>(mapf, 2);

    // proj(0), proj(1) on s1 overlap split(1), split(2)
    cudaStreamWaitEvent(s1, evS0, 0);
    k_gemm_proj1<<<dim3(8, 128), 256, NSTG * STAGEB, s1>>>(0, bf);
    cudaStreamWaitEvent(s1, evS1, 0);
    k_gemm_proj1<<<dim3(8, 128), 256, NSTG * STAGEB, s1>>>(1, br);
    cudaEventRecord(evP01, s1);

    // proj(2) on default (needs weights from s1)
    cudaStreamWaitEvent(0, evPrep, 0);
    k_gemm_proj1<<<dim3(8, 128), 256, NSTG * STAGEB>>>(2, bm);
    cudaStreamWaitEvent(0, evP01, 0);
    cudaEventRecord(evProj, 0);

    // branch A (s1): h -> aw
    cudaStreamWaitEvent(s1, evProj, 0);
    k_gemm_h<<<dim3(4, 128, 1), 256, NSTG * STAGEB, s1>>>(ba1);
    k_aw<<<BSZ / 4, 128, 0, s1>>>(Wa2, ba2);
    cudaEventRecord(evAw, s1);

    // branch B (default): qkv -> attn -> o
    k_gemm_qkv<<<dim3(24, 128, 3), 256, NSTG * STAGEB>>>();
    k_attn<<<BSZ, 128>>>();
    k_gemm_o<<<dim3(8, 384, 1), 256, NSTG * STAGEB>>>(bo);

    // join
    cudaStreamWaitEvent(0, evAw, 0);
    k_post1<<<BSZ, 128>>>(gamma1, beta1);
    k_gemm_gate<<<dim3(8, 128, 1), 256, NSTG * STAGEB>>>(bg);
    k_post2<<<BSZ, 128>>>(gamma2, beta2, (float*)d_out);
}